// round 14
// baseline (speedup 1.0000x reference)
#include <cuda_runtime.h>

#define NQ     1224
#define TWOQ   2448
#define SMAX   50
#define SM1    (SMAX - 1)
#define ROWS   (1024 * SM1)            // 50176
#define VEC4   (TWOQ / 4)              // 612 float4 per batch row
#define WPB    8
#define THREADS 256
#define RPW    4                       // rows per warp (4 concurrent streams)
#define BLOCKS (ROWS / (WPB * RPW))    // 1568
#define FULLM  0xffffffffu
#define NBUCK  64
#define BSTRIDE 32                     // pad buckets to separate 128B lines
#define CMAIN  608                     // last unguarded chunk base: c<=576 -> i0<=607

__device__ float    g_partials[NBUCK * BSTRIDE];   // zero-init at load
__device__ unsigned g_count;                        // zero-init at load

__device__ __forceinline__ unsigned nz4(const float4& v) {
    return __float_as_uint(v.x) | __float_as_uint(v.y) |
           __float_as_uint(v.z) | __float_as_uint(v.w);
}

__device__ __forceinline__ int locate4(const float4& v, int i) {
    int base = i * 4;
    if (v.x != 0.0f) return base;
    if (v.y != 0.0f) return base + 1;
    if (v.z != 0.0f) return base + 2;
    return base + 3;
}

// off(row) = (b*SMAX + t) * VEC4 with b = row/SM1, t = row%SM1 + 1
//          = (row + row/SM1 + 1) * VEC4     (32-bit safe: < 31.3M)
__device__ __forceinline__ int row_off4(int row) {
    return (row + row / SM1 + 1) * VEC4;
}
// pred row offset for (b, t-1): (b*SMAX + t - 1) * NQ = (row + row/SM1) * NQ
__device__ __forceinline__ int pred_off(int row) {
    return (row + row / SM1) * NQ;
}

__global__ __launch_bounds__(THREADS, 8)
void loss_kernel(const float* __restrict__ pred,
                 const float* __restrict__ batch,
                 float* __restrict__ out) {
    __shared__ float warp_part[WPB];

    const int wid  = threadIdx.x >> 5;
    const int lane = threadIdx.x & 31;
    const int gw   = blockIdx.x * WPB + wid;       // 0..12543

    const int row0 = gw * RPW;                      // 4 consecutive rows
    const int off0 = row_off4(row0);
    const int off1 = row_off4(row0 + 1);
    const int off2 = row_off4(row0 + 2);
    const int off3 = row_off4(row0 + 3);

    const float4* __restrict__ batch4 = (const float4*)batch;
    const float4 z = make_float4(0.f, 0.f, 0.f, 0.f);

    int j0 = -1, j1 = -1, j2 = -1, j3 = -1;

    // Four concurrent scan streams, 1 LDG.128/lane/stream (C = 128 floats):
    // detection granularity 128 -> expected overshoot only 64 floats/row.
    // Dead streams stop loading (predicated off) -> traffic saving.
    // Main loop: all chunks fully in-bounds (max i0 = 576+31 = 607 < 612).
    #pragma unroll 1
    for (int c = 0; c < CMAIN; c += 32) {
        const int i0 = c + lane;
        float4 v0 = z, v1 = z, v2 = z, v3 = z;
        if (j0 < 0) v0 = batch4[off0 + i0];
        if (j1 < 0) v1 = batch4[off1 + i0];
        if (j2 < 0) v2 = batch4[off2 + i0];
        if (j3 < 0) v3 = batch4[off3 + i0];

        const unsigned n0 = nz4(v0);
        const unsigned n1 = nz4(v1);
        const unsigned n2 = nz4(v2);
        const unsigned n3 = nz4(v3);

        if (__ballot_sync(FULLM, n0 | n1 | n2 | n3)) {
            // resolve whichever streams hit this chunk; resolved streams have
            // v==z so their redux returns -1; (js<0) guard never overwrites.
            int t;
            t = __reduce_max_sync(FULLM, n0 ? locate4(v0, i0) : -1);
            if (j0 < 0) j0 = t;
            t = __reduce_max_sync(FULLM, n1 ? locate4(v1, i0) : -1);
            if (j1 < 0) j1 = t;
            t = __reduce_max_sync(FULLM, n2 ? locate4(v2, i0) : -1);
            if (j2 < 0) j2 = t;
            t = __reduce_max_sync(FULLM, n3 ? locate4(v3, i0) : -1);
            if (j3 < 0) j3 = t;
            // all resolved? (OR is negative iff any j still -1)
            if ((j0 | j1 | j2 | j3) >= 0) break;
        }
    }

    // Tail chunk (c = 608): only lanes 0..3 are in-bounds (i0 < 612).
    if ((j0 | j1 | j2 | j3) < 0) {
        const int i0 = CMAIN + lane;
        const bool ib = (i0 < VEC4);
        float4 v0 = z, v1 = z, v2 = z, v3 = z;
        if (ib & (j0 < 0)) v0 = batch4[off0 + i0];
        if (ib & (j1 < 0)) v1 = batch4[off1 + i0];
        if (ib & (j2 < 0)) v2 = batch4[off2 + i0];
        if (ib & (j3 < 0)) v3 = batch4[off3 + i0];
        const unsigned n0 = nz4(v0);
        const unsigned n1 = nz4(v1);
        const unsigned n2 = nz4(v2);
        const unsigned n3 = nz4(v3);
        int t;
        t = __reduce_max_sync(FULLM, n0 ? locate4(v0, i0) : -1);
        if (j0 < 0) j0 = t;
        t = __reduce_max_sync(FULLM, n1 ? locate4(v1, i0) : -1);
        if (j1 < 0) j1 = t;
        t = __reduce_max_sync(FULLM, n2 ? locate4(v2, i0) : -1);
        if (j2 < 0) j2 = t;
        t = __reduce_max_sync(FULLM, n3 ? locate4(v3, i0) : -1);
        if (j3 < 0) j3 = t;
    }

    // Per-warp epilogue (lane 0): issue all 4 pred gathers back-to-back,
    // then the logs.
    if (lane == 0) {
        float contrib = 0.0f;
        float p0 = 0.f, p1 = 0.f, p2 = 0.f, p3 = 0.f;
        if (j0 >= 0)
            p0 = __ldg(pred + pred_off(row0)     + ((j0 < NQ) ? j0 : j0 - NQ));
        if (j1 >= 0)
            p1 = __ldg(pred + pred_off(row0 + 1) + ((j1 < NQ) ? j1 : j1 - NQ));
        if (j2 >= 0)
            p2 = __ldg(pred + pred_off(row0 + 2) + ((j2 < NQ) ? j2 : j2 - NQ));
        if (j3 >= 0)
            p3 = __ldg(pred + pred_off(row0 + 3) + ((j3 < NQ) ? j3 : j3 - NQ));
        if (j0 >= 0 && p0 > 0.0f) contrib -= __logf((j0 < NQ) ? p0 : 1.0f - p0);
        if (j1 >= 0 && p1 > 0.0f) contrib -= __logf((j1 < NQ) ? p1 : 1.0f - p1);
        if (j2 >= 0 && p2 > 0.0f) contrib -= __logf((j2 < NQ) ? p2 : 1.0f - p2);
        if (j3 >= 0 && p3 > 0.0f) contrib -= __logf((j3 < NQ) ? p3 : 1.0f - p3);
        warp_part[wid] = contrib;
    }
    __syncthreads();

    // CTA epilogue: bucketed atomic (1568 CTAs over 64 padded lines =
    // ~25 ops/address, invisible), last CTA folds the final reduction.
    if (threadIdx.x == 0) {
        float s = 0.0f;
        #pragma unroll
        for (int w = 0; w < WPB; ++w) s += warp_part[w];
        atomicAdd(&g_partials[(blockIdx.x & (NBUCK - 1)) * BSTRIDE], s);
        __threadfence();
        const unsigned prev = atomicAdd(&g_count, 1u);
        if (prev == BLOCKS - 1) {
            float tot = 0.0f;
            #pragma unroll
            for (int i = 0; i < NBUCK; ++i)
                tot += atomicExch(&g_partials[i * BSTRIDE], 0.0f); // read+reset
            out[0] = tot;
            atomicExch(&g_count, 0u);   // reset for next graph replay
        }
    }
}

extern "C" void kernel_launch(void* const* d_in, const int* in_sizes, int n_in,
                              void* d_out, int out_size) {
    const float* pred  = (const float*)d_in[0];
    const float* batch = (const float*)d_in[1];
    float* out = (float*)d_out;

    loss_kernel<<<BLOCKS, THREADS>>>(pred, batch, out);
}